// round 8
// baseline (speedup 1.0000x reference)
#include <cuda_runtime.h>
#include <cuda_bf16.h>
#include <mma.h>

using namespace nvcuda;

// Problem dims
#define BB    64
#define NN    512
#define DIN   256
#define DOUTD 256
#define DOP   64
#define MTOT  (BB*NN)      // 32768

// ---------------- scratch (static device globals; no runtime alloc) -------------
__device__ float g_Wcat[DIN * 4 * DOUTD];            // [256,1024] support|K|V|Q' (tf32-rounded)
__device__ float g_opWcat[DOP * 2 * DOUTD];          // [64,512] (tf32-rounded)
__device__ float g_biascat[2 * DOUTD];               // [512]
__device__ float g_Xr[(size_t)MTOT * DIN];           // tf32-rounded inputs
__device__ float g_OPr[(size_t)MTOT * DOP];          // tf32-rounded op_emb
__device__ float g_H[(size_t)MTOT * 4 * DOUTD];      // [32768,1024] sup(exact)|K|V|Q (rounded)
__device__ float g_SUPr[(size_t)MTOT * DOUTD];       // tf32-rounded support copy
__device__ float g_gates[(size_t)MTOT * 2 * DOUTD];  // [32768,512] pre-activation
__device__ float g_S[(size_t)BB * NN * NN];          // scores -> attn (in place)
__device__ float g_AS[(size_t)MTOT * DOUTD];         // adj @ support
__device__ float g_AV[(size_t)MTOT * DOUTD];         // attn @ Whv

__device__ __forceinline__ float tf32r(float v) { return wmma::__float_to_tf32(v); }

// ---------------- prep: pack + round weights ----------------
__global__ void prep_kernel(const float* __restrict__ dgf_W,
                            const float* __restrict__ Wk,
                            const float* __restrict__ Wv,
                            const float* __restrict__ Wq,
                            const float* __restrict__ a_w,
                            const float* __restrict__ dgf_opW,
                            const float* __restrict__ gat_opW,
                            const float* __restrict__ dgf_opb,
                            const float* __restrict__ gat_opb)
{
    int idx = blockIdx.x * blockDim.x + threadIdx.x;
    if (idx < DIN * 4 * DOUTD) {
        int i = idx >> 10;
        int j = idx & 1023;
        float v;
        if (j < 256)      v = dgf_W[i * 256 + j];
        else if (j < 512) v = Wk[(j - 256) * 256 + i];
        else if (j < 768) v = Wv[(j - 512) * 256 + i];
        else { int m = j - 768; v = Wq[m * 256 + i] * a_w[m] * 0.0625f; }
        g_Wcat[idx] = tf32r(v);
    }
    if (idx < DOP * 2 * DOUTD) {
        int k = idx >> 9;
        int j = idx & 511;
        g_opWcat[idx] = tf32r((j < 256) ? dgf_opW[j * 64 + k] : gat_opW[(j - 256) * 64 + k]);
    }
    if (idx < 2 * DOUTD) {
        g_biascat[idx] = (idx < 256) ? dgf_opb[idx] : gat_opb[idx - 256];
    }
}

// ---------------- tf32 round-copy ----------------
__global__ void round_copy(const float4* __restrict__ src, float4* __restrict__ dst, int n4)
{
    int i = blockIdx.x * blockDim.x + threadIdx.x;
    if (i < n4) {
        float4 v = src[i];
        v.x = tf32r(v.x); v.y = tf32r(v.y); v.z = tf32r(v.z); v.w = tf32r(v.w);
        dst[i] = v;
    }
}

// ---------------- cp.async helpers ----------------
__device__ __forceinline__ void cp16(void* dst, const void* src) {
    unsigned u = (unsigned)__cvta_generic_to_shared(dst);
    asm volatile("cp.async.cg.shared.global [%0], [%1], 16;" :: "r"(u), "l"(src));
}
__device__ __forceinline__ void cp_commit() { asm volatile("cp.async.commit_group;"); }
template <int P> __device__ __forceinline__ void cp_wait() {
    asm volatile("cp.async.wait_group %0;" :: "n"(P));
}

// ---------------- pipelined batched tf32 wmma GEMM: C = A @ B ----------------
// A row-major [M,K]. B row-major [K,N] (BCOL=0) or col-major (elem (k,n) at B[n*ldb+k], BCOL=1)
// CONVA=1: A loaded via LDG + tf32 round + STS (for non-pre-rounded A, e.g. adj)
// EPI=1: H mixed epilogue (bn<256: exact->C + rounded->C2; bn>=256: rounded->C)
constexpr int BK = 32;
constexpr int LDA_S  = BK + 8;    // 40
constexpr int LDB_SR = 128 + 8;   // 136
constexpr int LDB_SC = BK + 8;    // 40
constexpr int ASZ = 128 * LDA_S;  // floats per A stage

template <int BCOL, int CONVA, int EPI>
__global__ __launch_bounds__(256, 2)
void gemm2(const float* __restrict__ A, const float* __restrict__ B,
           float* __restrict__ C, float* __restrict__ C2,
           int M, int N, int K, int lda, int ldb, int ldc,
           size_t sA, size_t sB, size_t sC)
{
    extern __shared__ float sm[];
    constexpr int BSZ = BCOL ? (128 * LDB_SC) : (BK * LDB_SR);
    float* As = sm;              // 2 stages
    float* Bs = sm + 2 * ASZ;    // 2 stages

    A += (size_t)blockIdx.z * sA;
    B += (size_t)blockIdx.z * sB;
    C += (size_t)blockIdx.z * sC;

    const int bm = blockIdx.y * 128;
    const int bn = blockIdx.x * 128;
    const int tid = threadIdx.x;
    const int warp = tid >> 5;
    const int wm = (warp >> 1) * 32;
    const int wn = (warp & 1) * 64;

    // per-thread load coords
    const int ar = tid >> 3, ac = (tid & 7) * 4;           // A tile: rows ar+32*it
    const int br = tid >> 5, bc = (tid & 31) * 4;          // B row-major: rows br+8*it
    const int bnn = tid >> 3, bkc = (tid & 7) * 4;         // B col-major: cols bnn+32*it

    wmma::fragment<wmma::accumulator, 16, 16, 8, float> acc[2][4];
#pragma unroll
    for (int i = 0; i < 2; i++)
#pragma unroll
        for (int j = 0; j < 4; j++) wmma::fill_fragment(acc[i][j], 0.0f);

    const int T = K / BK;
    float4 av[4];

    // -------- stage-0 prologue --------
    if (CONVA) {
#pragma unroll
        for (int it = 0; it < 4; it++)
            av[it] = *(const float4*)(A + (size_t)(bm + ar + 32 * it) * lda + ac);
    } else {
#pragma unroll
        for (int it = 0; it < 4; it++)
            cp16(As + (ar + 32 * it) * LDA_S + ac,
                 A + (size_t)(bm + ar + 32 * it) * lda + ac);
    }
    if (BCOL == 0) {
#pragma unroll
        for (int it = 0; it < 4; it++)
            cp16(Bs + (br + 8 * it) * LDB_SR + bc,
                 B + (size_t)(br + 8 * it) * ldb + bn + bc);
    } else {
#pragma unroll
        for (int it = 0; it < 4; it++)
            cp16(Bs + (bnn + 32 * it) * LDB_SC + bkc,
                 B + (size_t)(bn + bnn + 32 * it) * ldb + bkc);
    }
    cp_commit();
    if (CONVA) {
#pragma unroll
        for (int it = 0; it < 4; it++) {
            float4 v = av[it];
            v.x = tf32r(v.x); v.y = tf32r(v.y); v.z = tf32r(v.z); v.w = tf32r(v.w);
            *(float4*)(As + (ar + 32 * it) * LDA_S + ac) = v;
        }
    }

    // -------- mainloop --------
    for (int i = 0; i < T; i++) {
        const int st = i & 1;
        const bool more = (i + 1 < T);
        if (more) {
            const int k0 = (i + 1) * BK;
            if (CONVA) {
#pragma unroll
                for (int it = 0; it < 4; it++)
                    av[it] = *(const float4*)(A + (size_t)(bm + ar + 32 * it) * lda + k0 + ac);
            } else {
#pragma unroll
                for (int it = 0; it < 4; it++)
                    cp16(As + (st ^ 1) * ASZ + (ar + 32 * it) * LDA_S + ac,
                         A + (size_t)(bm + ar + 32 * it) * lda + k0 + ac);
            }
            if (BCOL == 0) {
#pragma unroll
                for (int it = 0; it < 4; it++)
                    cp16(Bs + (st ^ 1) * BSZ + (br + 8 * it) * LDB_SR + bc,
                         B + (size_t)(k0 + br + 8 * it) * ldb + bn + bc);
            } else {
#pragma unroll
                for (int it = 0; it < 4; it++)
                    cp16(Bs + (st ^ 1) * BSZ + (bnn + 32 * it) * LDB_SC + bkc,
                         B + (size_t)(bn + bnn + 32 * it) * ldb + k0 + bkc);
            }
            cp_commit();
            cp_wait<1>();
        } else {
            cp_wait<0>();
        }
        __syncthreads();

        // compute stage st
        {
            const float* as = As + st * ASZ;
            const float* bs = Bs + st * BSZ;
#pragma unroll
            for (int kk = 0; kk < BK; kk += 8) {
                wmma::fragment<wmma::matrix_a, 16, 16, 8, wmma::precision::tf32, wmma::row_major> af[2];
#pragma unroll
                for (int ii = 0; ii < 2; ii++)
                    wmma::load_matrix_sync(af[ii], as + (wm + 16 * ii) * LDA_S + kk, LDA_S);
                if (BCOL == 0) {
                    wmma::fragment<wmma::matrix_b, 16, 16, 8, wmma::precision::tf32, wmma::row_major> bf[4];
#pragma unroll
                    for (int j = 0; j < 4; j++)
                        wmma::load_matrix_sync(bf[j], bs + kk * LDB_SR + wn + 16 * j, LDB_SR);
#pragma unroll
                    for (int ii = 0; ii < 2; ii++)
#pragma unroll
                        for (int j = 0; j < 4; j++)
                            wmma::mma_sync(acc[ii][j], af[ii], bf[j], acc[ii][j]);
                } else {
                    wmma::fragment<wmma::matrix_b, 16, 16, 8, wmma::precision::tf32, wmma::col_major> bf[4];
#pragma unroll
                    for (int j = 0; j < 4; j++)
                        wmma::load_matrix_sync(bf[j], bs + (wn + 16 * j) * LDB_SC + kk, LDB_SC);
#pragma unroll
                    for (int ii = 0; ii < 2; ii++)
#pragma unroll
                        for (int j = 0; j < 4; j++)
                            wmma::mma_sync(acc[ii][j], af[ii], bf[j], acc[ii][j]);
                }
            }
        }

        if (CONVA && more) {
#pragma unroll
            for (int it = 0; it < 4; it++) {
                float4 v = av[it];
                v.x = tf32r(v.x); v.y = tf32r(v.y); v.z = tf32r(v.z); v.w = tf32r(v.w);
                *(float4*)(As + (st ^ 1) * ASZ + (ar + 32 * it) * LDA_S + ac) = v;
            }
        }
        __syncthreads();
    }

    // -------- epilogue --------
    if (EPI == 0) {
#pragma unroll
        for (int ii = 0; ii < 2; ii++)
#pragma unroll
            for (int j = 0; j < 4; j++)
                wmma::store_matrix_sync(C + (size_t)(bm + wm + 16 * ii) * ldc + bn + wn + 16 * j,
                                        acc[ii][j], ldc, wmma::mem_row_major);
    } else {
        const bool kvq = (bn >= 256);
#pragma unroll
        for (int ii = 0; ii < 2; ii++)
#pragma unroll
            for (int j = 0; j < 4; j++) {
                if (kvq) {
#pragma unroll
                    for (int t = 0; t < acc[ii][j].num_elements; t++)
                        acc[ii][j].x[t] = tf32r(acc[ii][j].x[t]);
                    wmma::store_matrix_sync(C + (size_t)(bm + wm + 16 * ii) * ldc + bn + wn + 16 * j,
                                            acc[ii][j], ldc, wmma::mem_row_major);
                } else {
                    wmma::store_matrix_sync(C + (size_t)(bm + wm + 16 * ii) * ldc + bn + wn + 16 * j,
                                            acc[ii][j], ldc, wmma::mem_row_major);
                    wmma::fragment<wmma::accumulator, 16, 16, 8, float> r;
#pragma unroll
                    for (int t = 0; t < r.num_elements; t++)
                        r.x[t] = tf32r(acc[ii][j].x[t]);
                    wmma::store_matrix_sync(C2 + (size_t)(bm + wm + 16 * ii) * 256 + bn + wn + 16 * j,
                                            r, 256, wmma::mem_row_major);
                }
            }
    }
}

// ---------------- reductions ----------------
__device__ __forceinline__ float warp_max(float v) {
#pragma unroll
    for (int o = 16; o; o >>= 1) v = fmaxf(v, __shfl_xor_sync(0xffffffffu, v, o));
    return v;
}
__device__ __forceinline__ float warp_sum(float v) {
#pragma unroll
    for (int o = 16; o; o >>= 1) v += __shfl_xor_sync(0xffffffffu, v, o);
    return v;
}
__device__ __forceinline__ float block_max_256(float v, float* sh) {
    float w = warp_max(v);
    __syncthreads();
    if ((threadIdx.x & 31) == 0) sh[threadIdx.x >> 5] = w;
    __syncthreads();
    float t = sh[0];
#pragma unroll
    for (int i = 1; i < 8; i++) t = fmaxf(t, sh[i]);
    return t;
}
__device__ __forceinline__ float block_sum_256(float v, float* sh) {
    float w = warp_sum(v);
    __syncthreads();
    if ((threadIdx.x & 31) == 0) sh[threadIdx.x >> 5] = w;
    __syncthreads();
    float t = 0.0f;
#pragma unroll
    for (int i = 0; i < 8; i++) t += sh[i];
    return t;
}

// ---------------- leaky+mask+softmax over rows of S (in place, writes tf32) ----------------
__global__ void softmax_kernel(const float* __restrict__ adj)
{
    __shared__ float sh[8];
    const int r = blockIdx.x;
    float* Srow = g_S + (size_t)r * NN;
    const float* arow = adj + (size_t)r * NN;
    const int t = threadIdx.x;

    float v0 = Srow[t], v1 = Srow[t + 256];
    float a0 = arow[t], a1 = arow[t + 256];
    v0 = (v0 >= 0.0f ? v0 : 0.2f * v0) * a0;
    v1 = (v1 >= 0.0f ? v1 : 0.2f * v1) * a1;

    float m = block_max_256(fmaxf(v0, v1), sh);
    float e0 = expf(v0 - m), e1 = expf(v1 - m);
    float s = block_sum_256(e0 + e1, sh);
    float inv = 1.0f / s;
    Srow[t]       = tf32r(e0 * inv);
    Srow[t + 256] = tf32r(e1 * inv);
}

// ---------------- final: gates + dense residual + LN + blend ----------------
__global__ void final_kernel(const float* __restrict__ dgf_b,
                             const float* __restrict__ ln_g,
                             const float* __restrict__ ln_b,
                             float* __restrict__ out)
{
    __shared__ float sh[8];
    const size_t r = blockIdx.x;
    const int o = threadIdx.x;

    float sup = g_H[r * 1024 + o];
    float as  = g_AS[r * 256 + o];
    float av  = g_AV[r * 256 + o];
    float gd  = 1.0f / (1.0f + expf(-(g_gates[r * 512 + o] + g_biascat[o])));
    float gg  = 1.0f / (1.0f + expf(-(g_gates[r * 512 + 256 + o] + g_biascat[256 + o])));

    float dense = gd * as + sup + dgf_b[o];
    float h = gg * av;

    float mean = block_sum_256(h, sh) * (1.0f / 256.0f);
    float d = h - mean;
    float var = block_sum_256(d * d, sh) * (1.0f / 256.0f);
    float gat = d * rsqrtf(var + 1e-5f) * ln_g[o] + ln_b[o];

    out[r * 256 + o] = 0.5f * (dense + gat);
}

// ---------------- launch ----------------
extern "C" void kernel_launch(void* const* d_in, const int* in_sizes, int n_in,
                              void* d_out, int out_size)
{
    const float* inputs  = (const float*)d_in[0];
    const float* adj     = (const float*)d_in[1];
    const float* op_emb  = (const float*)d_in[2];
    const float* dgf_W   = (const float*)d_in[3];
    const float* dgf_b   = (const float*)d_in[4];
    const float* dgf_opW = (const float*)d_in[5];
    const float* dgf_opb = (const float*)d_in[6];
    const float* Wk      = (const float*)d_in[7];
    const float* Wv      = (const float*)d_in[8];
    const float* Wq      = (const float*)d_in[9];
    const float* a_w     = (const float*)d_in[10];
    const float* gat_opW = (const float*)d_in[11];
    const float* gat_opb = (const float*)d_in[12];
    const float* ln_g    = (const float*)d_in[13];
    const float* ln_b    = (const float*)d_in[14];
    float* out = (float*)d_out;

    float *H, *G, *S, *AS, *AV, *WC, *OWC, *Xr, *OPr, *SUPr;
    cudaGetSymbolAddress((void**)&H,    g_H);
    cudaGetSymbolAddress((void**)&G,    g_gates);
    cudaGetSymbolAddress((void**)&S,    g_S);
    cudaGetSymbolAddress((void**)&AS,   g_AS);
    cudaGetSymbolAddress((void**)&AV,   g_AV);
    cudaGetSymbolAddress((void**)&WC,   g_Wcat);
    cudaGetSymbolAddress((void**)&OWC,  g_opWcat);
    cudaGetSymbolAddress((void**)&Xr,   g_Xr);
    cudaGetSymbolAddress((void**)&OPr,  g_OPr);
    cudaGetSymbolAddress((void**)&SUPr, g_SUPr);

    const int SMEM_R = 4 * (2 * ASZ + 2 * (BK * LDB_SR));  // 75776 B (BCOL=0)
    const int SMEM_C = 4 * (2 * ASZ + 2 * (128 * LDB_SC)); // 81920 B (BCOL=1)
    cudaFuncSetAttribute(gemm2<0,0,1>, cudaFuncAttributeMaxDynamicSharedMemorySize, SMEM_R);
    cudaFuncSetAttribute(gemm2<0,0,0>, cudaFuncAttributeMaxDynamicSharedMemorySize, SMEM_R);
    cudaFuncSetAttribute(gemm2<0,1,0>, cudaFuncAttributeMaxDynamicSharedMemorySize, SMEM_R);
    cudaFuncSetAttribute(gemm2<1,0,0>, cudaFuncAttributeMaxDynamicSharedMemorySize, SMEM_C);

    // pack + round weights
    prep_kernel<<<1024, 256>>>(dgf_W, Wk, Wv, Wq, a_w, dgf_opW, gat_opW, dgf_opb, gat_opb);
    // pre-round activations feeding MMAs
    round_copy<<<(MTOT * DIN / 4 + 255) / 256, 256>>>((const float4*)inputs, (float4*)Xr, MTOT * DIN / 4);
    round_copy<<<(MTOT * DOP / 4 + 255) / 256, 256>>>((const float4*)op_emb, (float4*)OPr, MTOT * DOP / 4);

    // H = Xr @ Wcat   [32768,1024]  (mixed epilogue: sup exact + SUPr rounded, KVQ rounded)
    {
        dim3 grid(1024 / 128, MTOT / 128, 1);
        gemm2<0,0,1><<<grid, 256, SMEM_R>>>(Xr, WC, H, SUPr, MTOT, 1024, DIN,
                                            DIN, 1024, 1024, 0, 0, 0);
    }
    // gates = OPr @ opWcat  [32768,512]
    {
        dim3 grid(512 / 128, MTOT / 128, 1);
        gemm2<0,0,0><<<grid, 256, SMEM_R>>>(OPr, OWC, G, nullptr, MTOT, 512, DOP,
                                            DOP, 512, 512, 0, 0, 0);
    }
    // scores: S[b] = Whq' @ Whk^T  (B col-major view into H)
    {
        dim3 grid(NN / 128, NN / 128, BB);
        gemm2<1,0,0><<<grid, 256, SMEM_C>>>(H + 768, H + 256, S, nullptr, NN, NN, DOUTD,
                                            1024, 1024, NN,
                                            (size_t)NN * 1024, (size_t)NN * 1024, (size_t)NN * NN);
    }
    // leaky + adj mask + softmax (in place on S, writes tf32-rounded attn)
    softmax_kernel<<<MTOT, 256>>>(adj);

    // AV[b] = attn @ Whv
    {
        dim3 grid(DOUTD / 128, NN / 128, BB);
        gemm2<0,0,0><<<grid, 256, SMEM_R>>>(S, H + 512, AV, nullptr, NN, DOUTD, NN,
                                            NN, 1024, DOUTD,
                                            (size_t)NN * NN, (size_t)NN * 1024, (size_t)NN * DOUTD);
    }
    // AS[b] = adj @ SUPr  (adj rounded on the fly: CONVA=1)
    {
        dim3 grid(DOUTD / 128, NN / 128, BB);
        gemm2<0,1,0><<<grid, 256, SMEM_R>>>(adj, SUPr, AS, nullptr, NN, DOUTD, NN,
                                            NN, DOUTD, DOUTD,
                                            (size_t)NN * NN, (size_t)NN * DOUTD, (size_t)NN * DOUTD);
    }
    // gates + residual + LN + blend
    final_kernel<<<MTOT, 256>>>(dgf_b, ln_g, ln_b, out);

    (void)in_sizes; (void)n_in; (void)out_size;
}

// round 10
// speedup vs baseline: 2.1256x; 2.1256x over previous
#include <cuda_runtime.h>
#include <cuda_fp16.h>
#include <mma.h>
#include <cstdint>

using namespace nvcuda;

// Problem dims
#define BB    64
#define NN    512
#define DIN   256
#define DOUTD 256
#define DOP   64
#define MTOT  (BB*NN)      // 32768

// ---------------- scratch (static device globals) ----------------
__device__ __half g_WH[512 * 256];                    // rows 0-255: M^T (Q/K folded) | 256-511: dgf_W^T
__device__ __half g_Wcombh[512 * 256];                // rows 0-255: Wv | 256-511: dgf_W^T
__device__ __half g_Woph[512 * 64];                   // rows 0-255: dgf_opW | 256-511: gat_opW
__device__ float  g_biascat[512];
__device__ __half g_Xh[(size_t)MTOT * DIN];           // half inputs
__device__ __half g_OPh[(size_t)MTOT * DOP];          // half op_emb
__device__ __half g_Yh[(size_t)MTOT * 256];           // Y = X @ M (half)
__device__ float  g_SUP[(size_t)MTOT * 256];          // support (exact fp32)
__device__ float  g_G[(size_t)MTOT * 512];            // gate pre-acts
__device__ __half g_VSh[(size_t)BB * 512 * 512];      // per batch: rows 0-255 Whv^T | 256-511 support^T
__device__ float  g_S[(size_t)BB * NN * NN];          // scores (fp32)
__device__ __half g_attnh[(size_t)BB * NN * NN];      // softmax(attn) half
__device__ __half g_adjh[(size_t)BB * NN * NN];       // adj half
__device__ float  g_AV[(size_t)MTOT * 256];
__device__ float  g_AS[(size_t)MTOT * 256];

// ---------------- PTX helpers ----------------
__device__ __forceinline__ uint32_t smem_u32(const void* p) {
    uint32_t a;
    asm("{ .reg .u64 t; cvta.to.shared.u64 t, %1; cvt.u32.u64 %0, t; }" : "=r"(a) : "l"(p));
    return a;
}
__device__ __forceinline__ void cp16s(uint32_t dst, const void* src) {
    asm volatile("cp.async.cg.shared.global [%0], [%1], 16;" :: "r"(dst), "l"(src));
}

// ---------------- M^T precompute: g_WH[j,i] = sum_m Wq[m,i]*a_w[m]/16*Wk[m,j] ----------------
__global__ void mt_kernel(const float* __restrict__ Wq, const float* __restrict__ Wk,
                          const float* __restrict__ a_w)
{
    __shared__ float wk[256];
    const int j = blockIdx.x, i = threadIdx.x;
    wk[i] = Wk[i * 256 + j] * a_w[i] * 0.0625f;
    __syncthreads();
    float s = 0.0f;
#pragma unroll 8
    for (int m = 0; m < 256; m++) s += Wq[m * 256 + i] * wk[m];
    g_WH[j * 256 + i] = __float2half_rn(s);
}

// ---------------- prep: pack weights as half ----------------
__global__ void prep_kernel(const float* __restrict__ dgf_W,
                            const float* __restrict__ Wv,
                            const float* __restrict__ dgf_opW,
                            const float* __restrict__ gat_opW,
                            const float* __restrict__ dgf_opb,
                            const float* __restrict__ gat_opb)
{
    int idx = blockIdx.x * blockDim.x + threadIdx.x;
    if (idx < 256 * 256) {   // g_WH rows 256-511 = dgf_W^T
        int o = idx >> 8, i = idx & 255;
        g_WH[(256 + o) * 256 + i] = __float2half_rn(dgf_W[i * 256 + o]);
    }
    if (idx < 512 * 256) {   // g_Wcombh
        int m = idx >> 8, i = idx & 255;
        float v = (m < 256) ? Wv[m * 256 + i] : dgf_W[i * 256 + (m - 256)];
        g_Wcombh[idx] = __float2half_rn(v);
    }
    if (idx < 512 * 64) {
        int n = idx >> 6, p = idx & 63;
        float v = (n < 256) ? dgf_opW[n * 64 + p] : gat_opW[(n - 256) * 64 + p];
        g_Woph[idx] = __float2half_rn(v);
    }
    if (idx < 512) {
        g_biascat[idx] = (idx < 256) ? dgf_opb[idx] : gat_opb[idx - 256];
    }
}

// ---------------- float -> half copy ----------------
__global__ void f2h_copy(const float4* __restrict__ src, __half2* __restrict__ dst, int n4)
{
    int i = blockIdx.x * blockDim.x + threadIdx.x;
    if (i < n4) {
        float4 v = src[i];
        dst[2 * i]     = __floats2half2_rn(v.x, v.y);
        dst[2 * i + 1] = __floats2half2_rn(v.z, v.w);
    }
}

// ---------------- fp16 wmma GEMM: C[M,N] = A[M,K] @ B[N,K]^T ----------------
// 128x128 CTA tile, BK=64 (4 k=16 steps per tile), 2-stage cp.async pipeline.
// mode 0: fp32 out to Cf. mode 1: half out to Ch. mode 2: bn<256 -> half Ch @col bn, else fp32 Cf @col bn-256.
constexpr int BKH = 64;
constexpr int LDH = 72;                    // halfs per row (144B, 16B-aligned stride)
constexpr int STG = 128 * LDH;             // halfs per operand per stage

__global__ __launch_bounds__(256, 2)
void gemm_h(const __half* __restrict__ A, const __half* __restrict__ B,
            float* __restrict__ Cf, __half* __restrict__ Ch,
            int lda, int ldb, int ldcf, int ldch, int T, int mode,
            size_t sA, size_t sB, size_t sCf, size_t sCh)
{
    extern __shared__ __half smraw[];
    __half* sm = (__half*)(((uintptr_t)smraw + 127) & ~(uintptr_t)127);

    A += (size_t)blockIdx.z * sA;
    B += (size_t)blockIdx.z * sB;
    Cf += (size_t)blockIdx.z * sCf;
    Ch += (size_t)blockIdx.z * sCh;

    const int bm = blockIdx.y * 128, bn = blockIdx.x * 128;
    const int tid = threadIdx.x, warp = tid >> 5;
    const int wm = (warp >> 1) * 32, wn = (warp & 1) * 64;

    wmma::fragment<wmma::accumulator, 16, 16, 16, float> acc[2][4];
#pragma unroll
    for (int i = 0; i < 2; i++)
#pragma unroll
        for (int j = 0; j < 4; j++) wmma::fill_fragment(acc[i][j], 0.0f);

    auto load_stage = [&](int s, int t) {
        __half* as = sm + (size_t)s * 2 * STG;
        __half* bs = as + STG;
        const int k0 = t * BKH;
#pragma unroll
        for (int it = 0; it < 4; it++) {
            int idx = tid + it * 256;
            int rr = idx >> 3, cc = idx & 7;
            cp16s(smem_u32(as + rr * LDH + cc * 8),
                  A + (size_t)(bm + rr) * lda + k0 + cc * 8);
        }
#pragma unroll
        for (int it = 0; it < 4; it++) {
            int idx = tid + it * 256;
            int rr = idx >> 3, cc = idx & 7;
            cp16s(smem_u32(bs + rr * LDH + cc * 8),
                  B + (size_t)(bn + rr) * ldb + k0 + cc * 8);
        }
        asm volatile("cp.async.commit_group;");
    };

    load_stage(0, 0);

    for (int t = 0; t < T; t++) {
        const int s = t & 1;
        if (t + 1 < T) {
            load_stage(s ^ 1, t + 1);
            asm volatile("cp.async.wait_group 1;");
        } else {
            asm volatile("cp.async.wait_group 0;");
        }
        __syncthreads();

        const __half* as = sm + (size_t)s * 2 * STG;
        const __half* bs = as + STG;
#pragma unroll
        for (int kk = 0; kk < BKH; kk += 16) {
            wmma::fragment<wmma::matrix_a, 16, 16, 16, __half, wmma::row_major> af[2];
#pragma unroll
            for (int ii = 0; ii < 2; ii++)
                wmma::load_matrix_sync(af[ii], as + (wm + 16 * ii) * LDH + kk, LDH);
            wmma::fragment<wmma::matrix_b, 16, 16, 16, __half, wmma::col_major> bf[4];
#pragma unroll
            for (int j = 0; j < 4; j++)
                wmma::load_matrix_sync(bf[j], bs + (wn + 16 * j) * LDH + kk, LDH);
#pragma unroll
            for (int ii = 0; ii < 2; ii++)
#pragma unroll
                for (int j = 0; j < 4; j++)
                    wmma::mma_sync(acc[ii][j], af[ii], bf[j], acc[ii][j]);
        }
        __syncthreads();
    }

    // epilogue
    const bool half_out = (mode == 1) || (mode == 2 && bn < 256);
#pragma unroll
    for (int ii = 0; ii < 2; ii++)
#pragma unroll
        for (int j = 0; j < 4; j++) {
            const int row = bm + wm + 16 * ii;
            const int col = bn + wn + 16 * j;
            if (half_out) {
                wmma::fragment<wmma::accumulator, 16, 16, 16, __half> hf;
#pragma unroll
                for (int t = 0; t < hf.num_elements; t++)
                    hf.x[t] = __float2half_rn(acc[ii][j].x[t]);
                wmma::store_matrix_sync(Ch + (size_t)row * ldch + col, hf, ldch,
                                        wmma::mem_row_major);
            } else {
                const int cf = (mode == 2) ? (col - 256) : col;
                wmma::store_matrix_sync(Cf + (size_t)row * ldcf + cf, acc[ii][j], ldcf,
                                        wmma::mem_row_major);
            }
        }
}

// ---------------- reductions ----------------
__device__ __forceinline__ float warp_max(float v) {
#pragma unroll
    for (int o = 16; o; o >>= 1) v = fmaxf(v, __shfl_xor_sync(0xffffffffu, v, o));
    return v;
}
__device__ __forceinline__ float warp_sum(float v) {
#pragma unroll
    for (int o = 16; o; o >>= 1) v += __shfl_xor_sync(0xffffffffu, v, o);
    return v;
}
__device__ __forceinline__ float block_max_256(float v, float* sh) {
    float w = warp_max(v);
    __syncthreads();
    if ((threadIdx.x & 31) == 0) sh[threadIdx.x >> 5] = w;
    __syncthreads();
    float t = sh[0];
#pragma unroll
    for (int i = 1; i < 8; i++) t = fmaxf(t, sh[i]);
    return t;
}
__device__ __forceinline__ float block_sum_256(float v, float* sh) {
    float w = warp_sum(v);
    __syncthreads();
    if ((threadIdx.x & 31) == 0) sh[threadIdx.x >> 5] = w;
    __syncthreads();
    float t = 0.0f;
#pragma unroll
    for (int i = 0; i < 8; i++) t += sh[i];
    return t;
}

// ------- leaky+mask+softmax over rows of S -> attn (half); also emit adj (half) -------
__global__ void softmax_kernel(const float* __restrict__ adj)
{
    __shared__ float sh[8];
    const int r = blockIdx.x;
    const float* Srow = g_S + (size_t)r * NN;
    const float* arow = adj + (size_t)r * NN;
    __half* Orow = g_attnh + (size_t)r * NN;
    __half* Arow = g_adjh + (size_t)r * NN;
    const int t = threadIdx.x;

    float v0 = Srow[t], v1 = Srow[t + 256];
    float a0 = arow[t], a1 = arow[t + 256];
    Arow[t]       = __float2half_rn(a0);
    Arow[t + 256] = __float2half_rn(a1);
    v0 = (v0 >= 0.0f ? v0 : 0.2f * v0) * a0;
    v1 = (v1 >= 0.0f ? v1 : 0.2f * v1) * a1;

    float m = block_max_256(fmaxf(v0, v1), sh);
    float e0 = expf(v0 - m), e1 = expf(v1 - m);
    float s = block_sum_256(e0 + e1, sh);
    float inv = 1.0f / s;
    Orow[t]       = __float2half_rn(e0 * inv);
    Orow[t + 256] = __float2half_rn(e1 * inv);
}

// ---------------- final: gates + dense residual + LN + blend ----------------
__global__ void final_kernel(const float* __restrict__ dgf_b,
                             const float* __restrict__ ln_g,
                             const float* __restrict__ ln_b,
                             float* __restrict__ out)
{
    __shared__ float sh[8];
    const size_t r = blockIdx.x;
    const int o = threadIdx.x;

    float sup = g_SUP[r * 256 + o];
    float as  = g_AS[r * 256 + o];
    float av  = g_AV[r * 256 + o];
    float gd  = 1.0f / (1.0f + expf(-(g_G[r * 512 + o] + g_biascat[o])));
    float gg  = 1.0f / (1.0f + expf(-(g_G[r * 512 + 256 + o] + g_biascat[256 + o])));

    float dense = gd * as + sup + dgf_b[o];
    float h = gg * av;

    float mean = block_sum_256(h, sh) * (1.0f / 256.0f);
    float d = h - mean;
    float var = block_sum_256(d * d, sh) * (1.0f / 256.0f);
    float gat = d * rsqrtf(var + 1e-5f) * ln_g[o] + ln_b[o];

    out[r * 256 + o] = 0.5f * (dense + gat);
}

// ---------------- launch ----------------
extern "C" void kernel_launch(void* const* d_in, const int* in_sizes, int n_in,
                              void* d_out, int out_size)
{
    const float* inputs  = (const float*)d_in[0];
    const float* adj     = (const float*)d_in[1];
    const float* op_emb  = (const float*)d_in[2];
    const float* dgf_W   = (const float*)d_in[3];
    const float* dgf_b   = (const float*)d_in[4];
    const float* dgf_opW = (const float*)d_in[5];
    const float* dgf_opb = (const float*)d_in[6];
    const float* Wk      = (const float*)d_in[7];
    const float* Wv      = (const float*)d_in[8];
    const float* Wq      = (const float*)d_in[9];
    const float* a_w     = (const float*)d_in[10];
    const float* gat_opW = (const float*)d_in[11];
    const float* gat_opb = (const float*)d_in[12];
    const float* ln_g    = (const float*)d_in[13];
    const float* ln_b    = (const float*)d_in[14];
    float* out = (float*)d_out;

    __half *WH, *Wcombh, *Woph, *Xh, *OPh, *Yh, *VSh, *ATTh, *ADJh;
    float *SUP, *G, *S, *AV, *AS;
    cudaGetSymbolAddress((void**)&WH,     g_WH);
    cudaGetSymbolAddress((void**)&Wcombh, g_Wcombh);
    cudaGetSymbolAddress((void**)&Woph,   g_Woph);
    cudaGetSymbolAddress((void**)&Xh,     g_Xh);
    cudaGetSymbolAddress((void**)&OPh,    g_OPh);
    cudaGetSymbolAddress((void**)&Yh,     g_Yh);
    cudaGetSymbolAddress((void**)&VSh,    g_VSh);
    cudaGetSymbolAddress((void**)&ATTh,   g_attnh);
    cudaGetSymbolAddress((void**)&ADJh,   g_adjh);
    cudaGetSymbolAddress((void**)&SUP,    g_SUP);
    cudaGetSymbolAddress((void**)&G,      g_G);
    cudaGetSymbolAddress((void**)&S,      g_S);
    cudaGetSymbolAddress((void**)&AV,     g_AV);
    cudaGetSymbolAddress((void**)&AS,     g_AS);

    const int DSMEM = 2 * 2 * STG * (int)sizeof(__half) + 256;   // 2 stages x (A+B) + align pad
    cudaFuncSetAttribute(gemm_h, cudaFuncAttributeMaxDynamicSharedMemorySize, DSMEM);

    // weight prep
    mt_kernel<<<256, 256>>>(Wq, Wk, a_w);
    prep_kernel<<<512, 256>>>(dgf_W, Wv, dgf_opW, gat_opW, dgf_opb, gat_opb);
    // half copies of activations
    f2h_copy<<<(MTOT * DIN / 4 + 255) / 256, 256>>>((const float4*)inputs, (__half2*)Xh, MTOT * DIN / 4);
    f2h_copy<<<(MTOT * DOP / 4 + 255) / 256, 256>>>((const float4*)op_emb, (__half2*)OPh, MTOT * DOP / 4);

    // H: X @ [M | dgf_W]^T -> Y (half, cols 0-255) + support (fp32, cols 256-511)
    {
        dim3 grid(4, MTOT / 128, 1);
        gemm_h<<<grid, 256, DSMEM>>>(Xh, WH, SUP, Yh, 256, 256, 256, 256, 4, 2, 0, 0, 0, 0);
    }
    // gates: OPh @ Woph^T -> G fp32 [32768,512]
    {
        dim3 grid(4, MTOT / 128, 1);
        gemm_h<<<grid, 256, DSMEM>>>(OPh, Woph, G, Yh, 64, 64, 512, 0, 1, 0, 0, 0, 0, 0);
    }
    // VS[b] = Wcomb @ X[b]^T -> half [512,512] (rows 0-255 Whv^T, 256-511 support^T)
    {
        dim3 grid(4, 4, BB);
        gemm_h<<<grid, 256, DSMEM>>>(Wcombh, Xh, S, VSh, 256, 256, 0, 512, 4, 1,
                                     0, (size_t)512 * 256, 0, (size_t)512 * 512);
    }
    // scores: S[b] = Y[b] @ X[b]^T -> fp32
    {
        dim3 grid(4, 4, BB);
        gemm_h<<<grid, 256, DSMEM>>>(Yh, Xh, S, Yh, 256, 256, 512, 0, 4, 0,
                                     (size_t)512 * 256, (size_t)512 * 256, (size_t)512 * 512, 0);
    }
    // leaky + mask + softmax -> attn half; adj -> half
    softmax_kernel<<<MTOT, 256>>>(adj);

    // AV[b] = attn[b] @ (Whv^T)^T -> fp32 [512,256]
    {
        dim3 grid(2, 4, BB);
        gemm_h<<<grid, 256, DSMEM>>>(ATTh, VSh, AV, Yh, 512, 512, 256, 0, 8, 0,
                                     (size_t)512 * 512, (size_t)512 * 512, (size_t)512 * 256, 0);
    }
    // AS[b] = adj[b] @ (support^T)^T -> fp32 [512,256]
    {
        dim3 grid(2, 4, BB);
        gemm_h<<<grid, 256, DSMEM>>>(ADJh, VSh + (size_t)256 * 512, AS, Yh, 512, 512, 256, 0, 8, 0,
                                     (size_t)512 * 512, (size_t)512 * 512, (size_t)512 * 256, 0);
    }
    // gates + residual + LN + blend
    final_kernel<<<MTOT, 256>>>(dgf_b, ln_g, ln_b, out);

    (void)in_sizes; (void)n_in; (void)out_size;
}